// round 9
// baseline (speedup 1.0000x reference)
#include <cuda_runtime.h>

#define BSZ 2
#define DOP 32
#define RAN 128
#define AZI 128
#define ELE 32
#define NVOX (RAN*AZI*ELE)        /* 524288 */
#define TOTALV (BSZ*NVOX)         /* 1048576 */

#define DOPK_THREADS 256
#define DOPK_VPT 4
#define DOPK_BLOCKS (TOTALV/DOPK_VPT/DOPK_THREADS)   /* 1024 */
#define GATK_THREADS 256
#define GATK_VPT 2
#define GATK_BLOCKS (TOTALV/GATK_VPT/GATK_THREADS)   /* 2048 */

__device__ float4 g_xyz4[TOTALV];              /* interleaved (x,y,z,0): 16MB */
__device__ float  g_dop1[TOTALV];
__device__ float  g_dop2[TOTALV];
__device__ float  g_partials[GATK_BLOCKS];

// ---------------------------------------------------------------------------
// Kernel 1: xyz precompute (prologue) + streaming dop pass (VPT=4, float4)
// ---------------------------------------------------------------------------
__global__ __launch_bounds__(DOPK_THREADS) void dop_kernel(
    const float* __restrict__ x1,
    const float* __restrict__ gumbels,
    const float* __restrict__ dop_arr,
    const float* __restrict__ coords)
{
    __shared__ float s_dop[DOP];
    int t = blockIdx.x * blockDim.x + threadIdx.x;
    int g = t * DOPK_VPT;
    int b = g >> 19;
    int n = g & (NVOX - 1);

    if (threadIdx.x < DOP) s_dop[threadIdx.x] = dop_arr[b * DOP + threadIdx.x];

    // ---- xyz prologue (independent of s_dop) ----
    {
        const float* cb = coords + (size_t)b * 3 * NVOX;
        float4 r4 = __ldcs((const float4*)(cb + n));
        float4 a4 = __ldcs((const float4*)(cb + NVOX + n));
        float4 e4 = __ldcs((const float4*)(cb + 2 * NVOX + n));
        float rr[4] = {r4.x, r4.y, r4.z, r4.w};
        float aa[4] = {a4.x, a4.y, a4.z, a4.w};
        float ee[4] = {e4.x, e4.y, e4.z, e4.w};
        float4* ob = g_xyz4 + (size_t)b * NVOX + n;
#pragma unroll
        for (int j = 0; j < 4; j++) {
            float sa, ca, se, ce;
            __sincosf(aa[j], &sa, &ca);
            __sincosf(ee[j], &se, &ce);
            float rce = rr[j] * ce;
            ob[j] = make_float4(rce * ca, rce * sa, rr[j] * se, 0.0f);
        }
    }
    __syncthreads();

    const float* x1p = x1      + (size_t)b * DOP * NVOX + n;
    const float* gp  = gumbels + (size_t)b * DOP * NVOX + n;

    float sume[4]  = {0.f, 0.f, 0.f, 0.f};
    float wsum[4]  = {0.f, 0.f, 0.f, 0.f};
    float best[4]  = {-1e30f, -1e30f, -1e30f, -1e30f};
    float bestd[4] = {0.f, 0.f, 0.f, 0.f};

#pragma unroll 4
    for (int d = 0; d < DOP; d++) {
        float4 xv = __ldcs((const float4*)(x1p + (size_t)d * NVOX));
        float4 gv = __ldcs((const float4*)(gp  + (size_t)d * NVOX));
        float dv = s_dop[d];
        float xs[4] = {xv.x, xv.y, xv.z, xv.w};
        float gs[4] = {gv.x, gv.y, gv.z, gv.w};
#pragma unroll
        for (int j = 0; j < 4; j++) {
            float ev = __expf(xs[j]);
            sume[j] += ev;
            wsum[j] += ev * dv;
            float key = xs[j] + gs[j];
            if (key > best[j]) { best[j] = key; bestd[j] = dv; }
        }
    }

    int o = b * NVOX + n;
    *(float4*)(g_dop1 + o) = make_float4(bestd[0], bestd[1], bestd[2], bestd[3]);
    *(float4*)(g_dop2 + o) = make_float4(wsum[0] / sume[0], wsum[1] / sume[1],
                                         wsum[2] / sume[2], wsum[3] / sume[3]);
}

// ---------------------------------------------------------------------------
// Kernel 2: trilinear warp gather + loss partial sums (VPT=2, high occupancy)
// ---------------------------------------------------------------------------
__device__ __forceinline__ float fsig(float x) {
    return 1.0f / (1.0f + __expf(-x));
}

__global__ __launch_bounds__(GATK_THREADS) void gather_kernel(
    const float* __restrict__ seg,
    const float* __restrict__ flow,
    const float* __restrict__ ori)
{
    __shared__ float s_red[GATK_THREADS / 32];

    int t = blockIdx.x * blockDim.x + threadIdx.x;
    int g = t * GATK_VPT;
    int b = g >> 19;
    int n = g & (NVOX - 1);

    const float* fp = flow + (size_t)(b * NVOX + n) * 3;
    float2 fA = *(const float2*)(fp);
    float2 fB = *(const float2*)(fp + 2);
    float2 fC = *(const float2*)(fp + 4);
    float f[6] = {fA.x, fA.y, fB.x, fB.y, fC.x, fC.y};

    const float4* xb = g_xyz4 + (size_t)b * NVOX;

    const float* ob = ori + (size_t)b * 3 * NVOX;
    float2 r0 = *(const float2*)(ob + n);
    float2 r1 = *(const float2*)(ob + NVOX + n);
    float2 r2 = *(const float2*)(ob + 2 * NVOX + n);
    float o0[2] = {r0.x, r0.y};
    float o1[2] = {r1.x, r1.y};
    float o2[2] = {r2.x, r2.y};

    float2 sg2 = *(const float2*)(seg + (size_t)b * NVOX + n);
    float sg[2] = {sg2.x, sg2.y};

    float2 d12 = *(const float2*)(g_dop1 + b * NVOX + n);
    float2 d22 = *(const float2*)(g_dop2 + b * NVOX + n);
    float dd1[2] = {d12.x, d12.y};
    float dd2[2] = {d22.x, d22.y};

    float acc = 0.f;
#pragma unroll
    for (int j = 0; j < 2; j++) {
        int nn = n + j;
        int ei = nn & 31;
        int ai = (nn >> 5) & 127;
        int ri = nn >> 12;

        float ixf = fminf(fmaxf((float)ei + f[3*j + 0], 0.f), 31.f);
        float iyf = fminf(fmaxf((float)ai + f[3*j + 1], 0.f), 127.f);
        float izf = fminf(fmaxf((float)ri + f[3*j + 2], 0.f), 127.f);

        int x0 = (int)ixf;  float wx = ixf - (float)x0;  int x1i = min(x0 + 1, 31);
        int y0 = (int)iyf;  float wy = iyf - (float)y0;  int y1i = min(y0 + 1, 127);
        int z0 = (int)izf;  float wz = izf - (float)z0;  int z1i = min(z0 + 1, 127);

        float sxv = 0.f, syv = 0.f, szv = 0.f;
#pragma unroll
        for (int c = 0; c < 8; c++) {
            int   zz  = (c & 4) ? z1i : z0;
            float wzz = (c & 4) ? wz  : 1.f - wz;
            int   yy  = (c & 2) ? y1i : y0;
            float wyy = (c & 2) ? wy  : 1.f - wy;
            int   xx  = (c & 1) ? x1i : x0;
            float wxx = (c & 1) ? wx  : 1.f - wx;
            float w = wzz * wyy * wxx;
            float4 v = __ldg(xb + (zz * AZI + yy) * ELE + xx);
            sxv += w * v.x;
            syv += w * v.y;
            szv += w * v.z;
        }

        float4 own = xb[nn];
        float vx = (sxv - own.x) * 10.f;   // / INTERVAL(0.1)
        float vy = (syv - own.y) * 10.f;
        float vz = (szv - own.z) * 10.f;
        float lab = vx * o0[j] + vy * o1[j] + vz * o2[j];

        float d1 = lab - dd1[j];   d1 *= d1;
        float d2 = lab - dd2[j];   d2 *= d2;
        float s1 = fsig(10.f * (0.15f - d1));
        float s2 = fsig(10.f * (0.15f - d2));
        float sl = 0.5f * (s1 + s2);
        float ss = fsig(sg[j]);
        acc += fabsf(ss - sl);
    }

    // ---- deterministic per-block reduction (exact masks) ----
#pragma unroll
    for (int o = 16; o; o >>= 1) acc += __shfl_xor_sync(0xffffffffu, acc, o);
    if ((threadIdx.x & 31) == 0) s_red[threadIdx.x >> 5] = acc;
    __syncthreads();
    if (threadIdx.x < 32) {
        float v = (threadIdx.x < (GATK_THREADS / 32)) ? s_red[threadIdx.x] : 0.f;
#pragma unroll
        for (int o = 4; o; o >>= 1) v += __shfl_xor_sync(0xffffffffu, v, o);
        if (threadIdx.x == 0) g_partials[blockIdx.x] = v;
    }
}

// ---------------------------------------------------------------------------
// Kernel 3: final reduction of block partials -> scalar mean
// ---------------------------------------------------------------------------
__global__ __launch_bounds__(256) void final_kernel(float* __restrict__ out) {
    __shared__ float s_red[8];
    float v = 0.f;
    for (int i = threadIdx.x; i < GATK_BLOCKS; i += 256) v += g_partials[i];
#pragma unroll
    for (int o = 16; o; o >>= 1) v += __shfl_xor_sync(0xffffffffu, v, o);
    if ((threadIdx.x & 31) == 0) s_red[threadIdx.x >> 5] = v;
    __syncthreads();
    if (threadIdx.x < 32) {
        float w = (threadIdx.x < 8) ? s_red[threadIdx.x] : 0.f;
#pragma unroll
        for (int o = 4; o; o >>= 1) w += __shfl_xor_sync(0xffffffffu, w, o);
        if (threadIdx.x == 0) out[0] = w * (1.0f / (float)TOTALV);
    }
}

// ---------------------------------------------------------------------------
// Inputs (metadata order): seg, flow, x1, dop_arr, coords, ori, gumbels
// ---------------------------------------------------------------------------
extern "C" void kernel_launch(void* const* d_in, const int* in_sizes, int n_in,
                              void* d_out, int out_size) {
    const float* seg     = (const float*)d_in[0];
    const float* flow    = (const float*)d_in[1];
    const float* x1      = (const float*)d_in[2];
    const float* dop_arr = (const float*)d_in[3];
    const float* coords  = (const float*)d_in[4];
    const float* ori     = (const float*)d_in[5];
    const float* gumbels = (const float*)d_in[6];
    float* out = (float*)d_out;

    dop_kernel<<<DOPK_BLOCKS, DOPK_THREADS>>>(x1, gumbels, dop_arr, coords);
    gather_kernel<<<GATK_BLOCKS, GATK_THREADS>>>(seg, flow, ori);
    final_kernel<<<1, 256>>>(out);
}

// round 11
// speedup vs baseline: 1.0389x; 1.0389x over previous
#include <cuda_runtime.h>

#define BSZ 2
#define DOP 32
#define RAN 128
#define AZI 128
#define ELE 32
#define NVOX (RAN*AZI*ELE)        /* 524288 */
#define TOTALV (BSZ*NVOX)         /* 1048576 */

#define FUSE_THREADS 256
#define FUSE_VPT 2
#define FUSE_BLOCKS (TOTALV/FUSE_VPT/FUSE_THREADS)   /* 2048 */

__device__ float4 g_xyz4[TOTALV];              /* interleaved (x,y,z,0): 16MB */
__device__ float  g_partials[FUSE_BLOCKS];

// ---------------------------------------------------------------------------
// Kernel 1: xyz precompute (must complete before any gather reads neighbors)
// ---------------------------------------------------------------------------
__global__ __launch_bounds__(256) void xyz_kernel(const float* __restrict__ coords) {
    int t = blockIdx.x * blockDim.x + threadIdx.x;     // 0 .. TOTALV/4-1
    int g = t * 4;
    int b = g >> 19;
    int n = g & (NVOX - 1);
    const float* cb = coords + (size_t)b * 3 * NVOX;
    float4 r4 = __ldcs((const float4*)(cb + n));
    float4 a4 = __ldcs((const float4*)(cb + NVOX + n));
    float4 e4 = __ldcs((const float4*)(cb + 2 * NVOX + n));
    float rr[4] = {r4.x, r4.y, r4.z, r4.w};
    float aa[4] = {a4.x, a4.y, a4.z, a4.w};
    float ee[4] = {e4.x, e4.y, e4.z, e4.w};
    float4* ob = g_xyz4 + (size_t)b * NVOX + n;
#pragma unroll
    for (int j = 0; j < 4; j++) {
        float sa, ca, se, ce;
        __sincosf(aa[j], &sa, &ca);
        __sincosf(ee[j], &se, &ce);
        float rce = rr[j] * ce;
        ob[j] = make_float4(rce * ca, rce * sa, rr[j] * se, 0.0f);
    }
}

// ---------------------------------------------------------------------------
// Kernel 2: fused streaming dop pass + trilinear gather + loss partials
// ---------------------------------------------------------------------------
__device__ __forceinline__ float fsig(float x) {
    return 1.0f / (1.0f + __expf(-x));
}

__global__ __launch_bounds__(FUSE_THREADS) void fused_kernel(
    const float* __restrict__ x1,
    const float* __restrict__ gumbels,
    const float* __restrict__ dop_arr,
    const float* __restrict__ seg,
    const float* __restrict__ flow,
    const float* __restrict__ ori)
{
    __shared__ float s_dop[DOP];
    __shared__ float s_red[FUSE_THREADS / 32];

    int t = blockIdx.x * blockDim.x + threadIdx.x;
    int g = t * FUSE_VPT;
    int b = g >> 19;
    int n = g & (NVOX - 1);

    if (threadIdx.x < DOP) s_dop[threadIdx.x] = dop_arr[b * DOP + threadIdx.x];
    __syncthreads();

    // ---- streaming dop pass (R7 config: float2, unroll 8, evict-first) ----
    const float* x1p = x1      + (size_t)b * DOP * NVOX + n;
    const float* gp  = gumbels + (size_t)b * DOP * NVOX + n;

    float sume[2]  = {0.f, 0.f};
    float wsum[2]  = {0.f, 0.f};
    float best[2]  = {-1e30f, -1e30f};
    float bestd[2] = {0.f, 0.f};

#pragma unroll 8
    for (int d = 0; d < DOP; d++) {
        float2 xv = __ldcs((const float2*)(x1p + (size_t)d * NVOX));
        float2 gv = __ldcs((const float2*)(gp  + (size_t)d * NVOX));
        float dv = s_dop[d];
        float xs[2] = {xv.x, xv.y};
        float gs[2] = {gv.x, gv.y};
#pragma unroll
        for (int j = 0; j < 2; j++) {
            float ev = __expf(xs[j]);
            sume[j] += ev;
            wsum[j] += ev * dv;
            float key = xs[j] + gs[j];
            if (key > best[j]) { best[j] = key; bestd[j] = dv; }
        }
    }

    float dd1[2] = {bestd[0], bestd[1]};
    float dd2[2] = {wsum[0] / sume[0], wsum[1] / sume[1]};

    // ---- gather + loss tail ----
    const float* fp = flow + (size_t)(b * NVOX + n) * 3;
    float2 fA = *(const float2*)(fp);
    float2 fB = *(const float2*)(fp + 2);
    float2 fC = *(const float2*)(fp + 4);
    float f[6] = {fA.x, fA.y, fB.x, fB.y, fC.x, fC.y};

    const float4* xb = g_xyz4 + (size_t)b * NVOX;

    const float* ob = ori + (size_t)b * 3 * NVOX;
    float2 r0 = *(const float2*)(ob + n);
    float2 r1 = *(const float2*)(ob + NVOX + n);
    float2 r2 = *(const float2*)(ob + 2 * NVOX + n);
    float o0[2] = {r0.x, r0.y};
    float o1[2] = {r1.x, r1.y};
    float o2[2] = {r2.x, r2.y};

    float2 sg2 = *(const float2*)(seg + (size_t)b * NVOX + n);
    float sg[2] = {sg2.x, sg2.y};

    float acc = 0.f;
#pragma unroll
    for (int j = 0; j < 2; j++) {
        int nn = n + j;
        int ei = nn & 31;
        int ai = (nn >> 5) & 127;
        int ri = nn >> 12;

        float ixf = fminf(fmaxf((float)ei + f[3*j + 0], 0.f), 31.f);
        float iyf = fminf(fmaxf((float)ai + f[3*j + 1], 0.f), 127.f);
        float izf = fminf(fmaxf((float)ri + f[3*j + 2], 0.f), 127.f);

        int x0 = (int)ixf;  float wx = ixf - (float)x0;  int x1i = min(x0 + 1, 31);
        int y0 = (int)iyf;  float wy = iyf - (float)y0;  int y1i = min(y0 + 1, 127);
        int z0 = (int)izf;  float wz = izf - (float)z0;  int z1i = min(z0 + 1, 127);

        float sxv = 0.f, syv = 0.f, szv = 0.f;
#pragma unroll
        for (int c = 0; c < 8; c++) {
            int   zz  = (c & 4) ? z1i : z0;
            float wzz = (c & 4) ? wz  : 1.f - wz;
            int   yy  = (c & 2) ? y1i : y0;
            float wyy = (c & 2) ? wy  : 1.f - wy;
            int   xx  = (c & 1) ? x1i : x0;
            float wxx = (c & 1) ? wx  : 1.f - wx;
            float w = wzz * wyy * wxx;
            float4 v = __ldg(xb + (zz * AZI + yy) * ELE + xx);
            sxv += w * v.x;
            syv += w * v.y;
            szv += w * v.z;
        }

        float4 own = __ldg(xb + nn);
        float vx = (sxv - own.x) * 10.f;   // / INTERVAL(0.1)
        float vy = (syv - own.y) * 10.f;
        float vz = (szv - own.z) * 10.f;
        float lab = vx * o0[j] + vy * o1[j] + vz * o2[j];

        float d1 = lab - dd1[j];   d1 *= d1;
        float d2 = lab - dd2[j];   d2 *= d2;
        float s1 = fsig(10.f * (0.15f - d1));
        float s2 = fsig(10.f * (0.15f - d2));
        float sl = 0.5f * (s1 + s2);
        float ss = fsig(sg[j]);
        acc += fabsf(ss - sl);
    }

    // ---- deterministic per-block reduction (exact masks) ----
#pragma unroll
    for (int o = 16; o; o >>= 1) acc += __shfl_xor_sync(0xffffffffu, acc, o);
    if ((threadIdx.x & 31) == 0) s_red[threadIdx.x >> 5] = acc;
    __syncthreads();
    if (threadIdx.x < 32) {
        float v = (threadIdx.x < (FUSE_THREADS / 32)) ? s_red[threadIdx.x] : 0.f;
#pragma unroll
        for (int o = 4; o; o >>= 1) v += __shfl_xor_sync(0xffffffffu, v, o);
        if (threadIdx.x == 0) g_partials[blockIdx.x] = v;
    }
}

// ---------------------------------------------------------------------------
// Kernel 3: final reduction of block partials -> scalar mean
// ---------------------------------------------------------------------------
__global__ __launch_bounds__(256) void final_kernel(float* __restrict__ out) {
    __shared__ float s_red[8];
    float v = 0.f;
    for (int i = threadIdx.x; i < FUSE_BLOCKS; i += 256) v += g_partials[i];
#pragma unroll
    for (int o = 16; o; o >>= 1) v += __shfl_xor_sync(0xffffffffu, v, o);
    if ((threadIdx.x & 31) == 0) s_red[threadIdx.x >> 5] = v;
    __syncthreads();
    if (threadIdx.x < 32) {
        float w = (threadIdx.x < 8) ? s_red[threadIdx.x] : 0.f;
#pragma unroll
        for (int o = 4; o; o >>= 1) w += __shfl_xor_sync(0xffffffffu, w, o);
        if (threadIdx.x == 0) out[0] = w * (1.0f / (float)TOTALV);
    }
}

// ---------------------------------------------------------------------------
// Inputs (metadata order): seg, flow, x1, dop_arr, coords, ori, gumbels
// ---------------------------------------------------------------------------
extern "C" void kernel_launch(void* const* d_in, const int* in_sizes, int n_in,
                              void* d_out, int out_size) {
    const float* seg     = (const float*)d_in[0];
    const float* flow    = (const float*)d_in[1];
    const float* x1      = (const float*)d_in[2];
    const float* dop_arr = (const float*)d_in[3];
    const float* coords  = (const float*)d_in[4];
    const float* ori     = (const float*)d_in[5];
    const float* gumbels = (const float*)d_in[6];
    float* out = (float*)d_out;

    xyz_kernel<<<TOTALV / 4 / 256, 256>>>(coords);
    fused_kernel<<<FUSE_BLOCKS, FUSE_THREADS>>>(x1, gumbels, dop_arr, seg, flow, ori);
    final_kernel<<<1, 256>>>(out);
}